// round 1
// baseline (speedup 1.0000x reference)
#include <cuda_runtime.h>
#include <math.h>

#define BB 2
#define SS 2048
#define DD 1024
#define HH 16
#define HDD 64
#define MTOT (BB * SS)      // 4096
#define NQKV (3 * DD)       // 3072

// Scratch (device globals — no allocation allowed)
__device__ float g_qkv[MTOT * NQKV];        // [B,S,3,H,HD]  48 MB
__device__ float g_q[BB * HH * SS * HDD];   // [B,H,S,HD]    16 MB
__device__ float g_k[BB * HH * SS * HDD];
__device__ float g_v[BB * HH * SS * HDD];
__device__ float g_attn[MTOT * DD];         // [B,S,D]       16 MB

// ---------------------------------------------------------------------------
// SGEMM: C[M,N] = A[M,K] @ W[N,K]^T + bias[N]
// 128x128 tile, BK=8, 256 threads, 8x8 per-thread (split as 2x 4-chunks at
// offsets {0,64} for conflict-free LDS.128).
// Requires M%128==0, N%128==0, K%8==0.
// ---------------------------------------------------------------------------
__global__ void __launch_bounds__(256) sgemm_bias_tn(
    const float* __restrict__ A, const float* __restrict__ W,
    const float* __restrict__ bias, float* __restrict__ C,
    int M, int N, int K)
{
    __shared__ float As[8][128];
    __shared__ float Bs[8][128];

    const int tid  = threadIdx.x;
    const int bm   = blockIdx.y << 7;
    const int bn   = blockIdx.x << 7;
    const int lrow = tid >> 1;          // 0..127
    const int lcol = (tid & 1) << 2;    // 0 or 4
    const int tx   = tid & 15;
    const int ty   = tid >> 4;

    const float* Ap = A + (size_t)(bm + lrow) * K + lcol;
    const float* Wp = W + (size_t)(bn + lrow) * K + lcol;

    float acc[8][8];
    #pragma unroll
    for (int i = 0; i < 8; i++)
        #pragma unroll
        for (int j = 0; j < 8; j++) acc[i][j] = 0.f;

    for (int k0 = 0; k0 < K; k0 += 8) {
        float4 a = *(const float4*)(Ap + k0);
        float4 w = *(const float4*)(Wp + k0);
        As[lcol + 0][lrow] = a.x; As[lcol + 1][lrow] = a.y;
        As[lcol + 2][lrow] = a.z; As[lcol + 3][lrow] = a.w;
        Bs[lcol + 0][lrow] = w.x; Bs[lcol + 1][lrow] = w.y;
        Bs[lcol + 2][lrow] = w.z; Bs[lcol + 3][lrow] = w.w;
        __syncthreads();

        #pragma unroll
        for (int kk = 0; kk < 8; kk++) {
            float4 a0 = *(const float4*)&As[kk][(ty << 2)];
            float4 a1 = *(const float4*)&As[kk][64 + (ty << 2)];
            float4 b0 = *(const float4*)&Bs[kk][(tx << 2)];
            float4 b1 = *(const float4*)&Bs[kk][64 + (tx << 2)];
            float ra[8] = {a0.x, a0.y, a0.z, a0.w, a1.x, a1.y, a1.z, a1.w};
            float rb[8] = {b0.x, b0.y, b0.z, b0.w, b1.x, b1.y, b1.z, b1.w};
            #pragma unroll
            for (int i = 0; i < 8; i++)
                #pragma unroll
                for (int j = 0; j < 8; j++)
                    acc[i][j] = fmaf(ra[i], rb[j], acc[i][j]);
        }
        __syncthreads();
    }

    #pragma unroll
    for (int ri = 0; ri < 2; ri++) {
        #pragma unroll
        for (int i = 0; i < 4; i++) {
            const int row = bm + (ri << 6) + (ty << 2) + i;
            #pragma unroll
            for (int ci = 0; ci < 2; ci++) {
                const int col = bn + (ci << 6) + (tx << 2);
                float4 bi = *(const float4*)&bias[col];
                float4 o;
                o.x = acc[(ri << 2) + i][(ci << 2) + 0] + bi.x;
                o.y = acc[(ri << 2) + i][(ci << 2) + 1] + bi.y;
                o.z = acc[(ri << 2) + i][(ci << 2) + 2] + bi.z;
                o.w = acc[(ri << 2) + i][(ci << 2) + 3] + bi.w;
                *(float4*)&C[(size_t)row * N + col] = o;
            }
        }
    }
}

// ---------------------------------------------------------------------------
// RoPE + split/transpose: qkv[B,S,3,H,HD] -> q,k (rotated), v in [B,H,S,HD]
// One thread per (b,s,h,i), i in [0,32): handles the (2i, 2i+1) pair.
// ---------------------------------------------------------------------------
__global__ void rope_split_kernel(const float* __restrict__ qkv,
                                  const float* __restrict__ freqs,
                                  float* __restrict__ q,
                                  float* __restrict__ k,
                                  float* __restrict__ v)
{
    const int idx = blockIdx.x * blockDim.x + threadIdx.x;  // 2^21 total
    const int i = idx & 31;
    const int h = (idx >> 5) & 15;
    const int s = (idx >> 9) & 2047;
    const int b = idx >> 20;

    const float f = freqs[s * 32 + i];
    const float c  = cosf(f);
    const float sn = sinf(f);

    const float* base = qkv + (size_t)(b * SS + s) * NQKV + h * HDD + 2 * i;
    const float q0 = base[0],          q1 = base[1];
    const float k0 = base[DD],         k1 = base[DD + 1];
    const float v0 = base[2 * DD],     v1 = base[2 * DD + 1];

    const size_t o = ((size_t)((b * HH + h) * SS) + s) * HDD + 2 * i;
    q[o]     = q0 * c - q1 * sn;
    q[o + 1] = q0 * sn + q1 * c;
    k[o]     = k0 * c - k1 * sn;
    k[o + 1] = k0 * sn + k1 * c;
    v[o]     = v0;
    v[o + 1] = v1;
}

// ---------------------------------------------------------------------------
// Flash attention, fp32, causal. BQ=BK=64, HD=64, 256 threads (16x16).
// Q/K stored transposed [d][m] in smem (pitch 68), V direct [k][c], P [r][k].
// Writes O directly into [B,S,D] layout for the proj GEMM.
// ---------------------------------------------------------------------------
#define FA_PITCH 68
#define FA_SMEM (4 * 64 * FA_PITCH * 4)   // 69632 bytes

__global__ void __launch_bounds__(256) flash_attn_kernel(
    const float* __restrict__ Q, const float* __restrict__ K,
    const float* __restrict__ V, float* __restrict__ O)
{
    extern __shared__ float sm[];
    float* Qs = sm;
    float* Ks = sm + 64 * FA_PITCH;
    float* Vs = sm + 2 * 64 * FA_PITCH;
    float* Ps = sm + 3 * 64 * FA_PITCH;

    const int tid = threadIdx.x;
    const int tx  = tid & 15;
    const int ty  = tid >> 4;
    const int q0  = blockIdx.x << 6;
    const int bh  = blockIdx.y;

    const float* Qb = Q + ((size_t)bh * SS + q0) * HDD;
    const float* Kb = K + (size_t)bh * SS * HDD;
    const float* Vb = V + (size_t)bh * SS * HDD;

    // Load Q tile, pre-scaled by 1/sqrt(HD), transposed -> Qs[d][m]
    #pragma unroll 4
    for (int idx = tid; idx < 1024; idx += 256) {
        const int r  = idx >> 4;
        const int d4 = (idx & 15) << 2;
        float4 t = *(const float4*)(Qb + r * HDD + d4);
        Qs[(d4 + 0) * FA_PITCH + r] = t.x * 0.125f;
        Qs[(d4 + 1) * FA_PITCH + r] = t.y * 0.125f;
        Qs[(d4 + 2) * FA_PITCH + r] = t.z * 0.125f;
        Qs[(d4 + 3) * FA_PITCH + r] = t.w * 0.125f;
    }

    float mrow[4], lrow[4], acc[4][4];
    #pragma unroll
    for (int i = 0; i < 4; i++) {
        mrow[i] = -1e30f;
        lrow[i] = 0.f;
        #pragma unroll
        for (int j = 0; j < 4; j++) acc[i][j] = 0.f;
    }

    const int ntiles = (q0 >> 6) + 1;
    for (int t = 0; t < ntiles; t++) {
        const int k0 = t << 6;
        __syncthreads();   // previous tile's Ps/Vs reads done
        #pragma unroll 4
        for (int idx = tid; idx < 1024; idx += 256) {
            const int r  = idx >> 4;
            const int d4 = (idx & 15) << 2;
            float4 kt = *(const float4*)(Kb + (size_t)(k0 + r) * HDD + d4);
            Ks[(d4 + 0) * FA_PITCH + r] = kt.x;
            Ks[(d4 + 1) * FA_PITCH + r] = kt.y;
            Ks[(d4 + 2) * FA_PITCH + r] = kt.z;
            Ks[(d4 + 3) * FA_PITCH + r] = kt.w;
            float4 vt = *(const float4*)(Vb + (size_t)(k0 + r) * HDD + d4);
            *(float4*)&Vs[r * FA_PITCH + d4] = vt;
        }
        __syncthreads();

        // S = Q K^T (pre-scaled)
        float sc[4][4] = {};
        #pragma unroll
        for (int d = 0; d < 64; d++) {
            float4 a = *(const float4*)&Qs[d * FA_PITCH + (ty << 2)];
            float4 b = *(const float4*)&Ks[d * FA_PITCH + (tx << 2)];
            float ra[4] = {a.x, a.y, a.z, a.w};
            float rb[4] = {b.x, b.y, b.z, b.w};
            #pragma unroll
            for (int i = 0; i < 4; i++)
                #pragma unroll
                for (int j = 0; j < 4; j++)
                    sc[i][j] = fmaf(ra[i], rb[j], sc[i][j]);
        }

        // Causal mask (only the diagonal tile needs it)
        if (k0 == q0) {
            #pragma unroll
            for (int i = 0; i < 4; i++)
                #pragma unroll
                for (int j = 0; j < 4; j++)
                    if ((tx << 2) + j > (ty << 2) + i) sc[i][j] = -1e30f;
        }

        // Online softmax (row reductions across the 16-lane tx group)
        #pragma unroll
        for (int i = 0; i < 4; i++) {
            float rm = fmaxf(fmaxf(sc[i][0], sc[i][1]), fmaxf(sc[i][2], sc[i][3]));
            #pragma unroll
            for (int m = 1; m < 16; m <<= 1)
                rm = fmaxf(rm, __shfl_xor_sync(0xffffffffu, rm, m));
            const float mnew = fmaxf(mrow[i], rm);
            const float corr = __expf(mrow[i] - mnew);
            mrow[i] = mnew;
            float rs = 0.f;
            #pragma unroll
            for (int j = 0; j < 4; j++) {
                sc[i][j] = __expf(sc[i][j] - mnew);
                rs += sc[i][j];
            }
            #pragma unroll
            for (int m = 1; m < 16; m <<= 1)
                rs += __shfl_xor_sync(0xffffffffu, rs, m);
            lrow[i] = lrow[i] * corr + rs;
            #pragma unroll
            for (int j = 0; j < 4; j++) acc[i][j] *= corr;
            *(float4*)&Ps[((ty << 2) + i) * FA_PITCH + (tx << 2)] =
                make_float4(sc[i][0], sc[i][1], sc[i][2], sc[i][3]);
        }
        __syncthreads();

        // O += P @ V
        #pragma unroll
        for (int kk = 0; kk < 64; kk++) {
            float4 v4 = *(const float4*)&Vs[kk * FA_PITCH + (tx << 2)];
            float rv[4] = {v4.x, v4.y, v4.z, v4.w};
            #pragma unroll
            for (int i = 0; i < 4; i++) {
                const float p = Ps[((ty << 2) + i) * FA_PITCH + kk];
                #pragma unroll
                for (int j = 0; j < 4; j++)
                    acc[i][j] = fmaf(p, rv[j], acc[i][j]);
            }
        }
    }

    // Epilogue: normalize, write into [B,S,D]
    const int b = bh >> 4;
    const int h = bh & 15;
    float* Ob = O + ((size_t)(b * SS + q0)) * DD + h * HDD;
    #pragma unroll
    for (int i = 0; i < 4; i++) {
        const float inv = 1.f / lrow[i];
        *(float4*)&Ob[(size_t)((ty << 2) + i) * DD + (tx << 2)] =
            make_float4(acc[i][0] * inv, acc[i][1] * inv,
                        acc[i][2] * inv, acc[i][3] * inv);
    }
}

// ---------------------------------------------------------------------------
// Launch
// ---------------------------------------------------------------------------
extern "C" void kernel_launch(void* const* d_in, const int* in_sizes, int n_in,
                              void* d_out, int out_size)
{
    const float* x      = (const float*)d_in[0];
    // d_in[1] = attn_mask (bool tril) — causal, handled analytically
    const float* freqs  = (const float*)d_in[2];
    const float* w_qkv  = (const float*)d_in[3];
    const float* b_qkv  = (const float*)d_in[4];
    const float* w_proj = (const float*)d_in[5];
    const float* b_proj = (const float*)d_in[6];
    float* out = (float*)d_out;

    float *qkv_p, *q_p, *k_p, *v_p, *attn_p;
    cudaGetSymbolAddress((void**)&qkv_p,  g_qkv);
    cudaGetSymbolAddress((void**)&q_p,    g_q);
    cudaGetSymbolAddress((void**)&k_p,    g_k);
    cudaGetSymbolAddress((void**)&v_p,    g_v);
    cudaGetSymbolAddress((void**)&attn_p, g_attn);

    cudaFuncSetAttribute(flash_attn_kernel,
                         cudaFuncAttributeMaxDynamicSharedMemorySize, FA_SMEM);

    // 1) QKV = x @ w_qkv^T + b_qkv          (4096 x 3072 x 1024)
    sgemm_bias_tn<<<dim3(NQKV / 128, MTOT / 128), 256>>>(
        x, w_qkv, b_qkv, qkv_p, MTOT, NQKV, DD);

    // 2) RoPE + split into [B,H,S,HD]
    rope_split_kernel<<<(BB * SS * HH * (HDD / 2)) / 256, 256>>>(
        qkv_p, freqs, q_p, k_p, v_p);

    // 3) Causal flash attention -> [B,S,D]
    flash_attn_kernel<<<dim3(SS / 64, BB * HH), 256, FA_SMEM>>>(
        q_p, k_p, v_p, attn_p);

    // 4) out = attn @ w_proj^T + b_proj     (4096 x 1024 x 1024)
    sgemm_bias_tn<<<dim3(DD / 128, MTOT / 128), 256>>>(
        attn_p, w_proj, b_proj, out, MTOT, DD, DD);
}

// round 3
// speedup vs baseline: 3.0167x; 3.0167x over previous
#include <cuda_runtime.h>
#include <cstdint>
#include <math.h>

#define BB 2
#define SS 2048
#define DD 1024
#define HH 16
#define HDD 64
#define MTOT (BB * SS)      // 4096
#define NQKV (3 * DD)       // 3072

// ---------------- device scratch (no allocation allowed) -------------------
__device__ float g_qkv[MTOT * NQKV];        // 48 MB
__device__ float g_q[BB * HH * SS * HDD];   // 16 MB
__device__ float g_k[BB * HH * SS * HDD];
__device__ float g_v[BB * HH * SS * HDD];
__device__ float g_attn[MTOT * DD];         // 16 MB (tf32-rounded by flash epilogue)
__device__ float g_xr[MTOT * DD];           // tf32-rounded x
__device__ float g_wqkvr[NQKV * DD];        // tf32-rounded w_qkv
__device__ float g_wprojr[DD * DD];         // tf32-rounded w_proj

// ---------------- helpers ---------------------------------------------------
__device__ __forceinline__ uint32_t smem_u32(const void* p) {
    uint32_t a;
    asm("{ .reg .u64 t; cvta.to.shared.u64 t, %1; cvt.u32.u64 %0, t; }"
        : "=r"(a) : "l"(p));
    return a;
}
__device__ __forceinline__ float tf32r(float x) {
    float y;
    asm("cvt.rna.tf32.f32 %0, %1;" : "=f"(y) : "f"(x));
    return y;
}
__device__ __forceinline__ void mma_tf32(
    float& c0, float& c1, float& c2, float& c3,
    uint32_t a0, uint32_t a1, uint32_t a2, uint32_t a3,
    uint32_t b0, uint32_t b1)
{
    asm volatile(
        "mma.sync.aligned.m16n8k8.row.col.f32.tf32.tf32.f32 "
        "{%0,%1,%2,%3}, {%4,%5,%6,%7}, {%8,%9}, {%0,%1,%2,%3};"
        : "+f"(c0), "+f"(c1), "+f"(c2), "+f"(c3)
        : "r"(a0), "r"(a1), "r"(a2), "r"(a3), "r"(b0), "r"(b1));
}
#define CPASYNC16(dst, src) \
    asm volatile("cp.async.cg.shared.global [%0], [%1], 16;" :: "r"(dst), "l"(src))
#define CPCOMMIT() asm volatile("cp.async.commit_group;")

// ---------------------------------------------------------------------------
// tf32 mma.sync GEMM: C[M,N] = A[M,K] @ W[N,K]^T + bias[N]
// 128x128 CTA tile, 256 thr (8 warps: 2x4 m/n, 64x32 each), BK=32,
// 3-stage cp.async pipeline. Inputs must be tf32-pre-rounded.
// Requires M%128==0, N%128==0, K%32==0, K/32 >= 3.
// ---------------------------------------------------------------------------
#define GSTAGES 3
#define GSTRIDE 36                          // floats per smem row (32 + pad 4)
#define GTILE_B (128 * GSTRIDE * 4)         // 18432 bytes (one operand)
#define GSTAGE_B (2 * GTILE_B)              // 36864
#define GEMM_SMEM (GSTAGES * GSTAGE_B)      // 110592

__device__ __forceinline__ void g_load_stage(
    uint32_t sbase, const float* A, const float* W, int K,
    int bm, int bn, int buf, int it, int tid)
{
    uint32_t sa = sbase + buf * GSTAGE_B;
    uint32_t sw = sa + GTILE_B;
    const float* Ag = A + (size_t)bm * K + it * 32;
    const float* Wg = W + (size_t)bn * K + it * 32;
    #pragma unroll
    for (int i = 0; i < 4; i++) {
        int idx = tid + (i << 8);           // 0..1023
        int row = idx >> 3, c = idx & 7;    // 16B chunk
        uint32_t off = row * (GSTRIDE * 4) + (c << 4);
        CPASYNC16(sa + off, Ag + (size_t)row * K + (c << 2));
        CPASYNC16(sw + off, Wg + (size_t)row * K + (c << 2));
    }
    CPCOMMIT();
}

__global__ void __launch_bounds__(256) gemm_mma_tf32(
    const float* __restrict__ A, const float* __restrict__ W,
    const float* __restrict__ bias, float* __restrict__ C,
    int M, int N, int K)
{
    extern __shared__ char smem[];
    uint32_t sb = smem_u32(smem);
    const int tid  = threadIdx.x;
    const int lane = tid & 31;
    const int wid  = tid >> 5;
    const int wm   = wid >> 2;              // 0..1
    const int wn   = wid & 3;               // 0..3
    const int bm = blockIdx.y << 7, bn = blockIdx.x << 7;
    const int lr = lane >> 2;               // 0..7
    const int lq = lane & 3;                // 0..3

    float acc[4][4][4];
    #pragma unroll
    for (int mi = 0; mi < 4; mi++)
        #pragma unroll
        for (int ni = 0; ni < 4; ni++)
            #pragma unroll
            for (int e = 0; e < 4; e++) acc[mi][ni][e] = 0.f;

    const int niter = K >> 5;
    for (int s = 0; s < GSTAGES; s++) g_load_stage(sb, A, W, K, bm, bn, s, s, tid);

    const float* AsF;
    for (int i = 0; i < niter; i++) {
        const int buf = i % GSTAGES;
        asm volatile("cp.async.wait_group 2;" ::: "memory");
        __syncthreads();

        const uint32_t* As = (const uint32_t*)(smem + buf * GSTAGE_B);
        const uint32_t* Ws = (const uint32_t*)(smem + buf * GSTAGE_B + GTILE_B);
        #pragma unroll
        for (int ks = 0; ks < 4; ks++) {
            const int kc = (ks << 3) + lq;
            uint32_t af[4][4], bf[4][2];
            #pragma unroll
            for (int mi = 0; mi < 4; mi++) {
                const int r = (wm << 6) + (mi << 4) + lr;
                af[mi][0] = As[r * GSTRIDE + kc];
                af[mi][1] = As[(r + 8) * GSTRIDE + kc];
                af[mi][2] = As[r * GSTRIDE + kc + 4];
                af[mi][3] = As[(r + 8) * GSTRIDE + kc + 4];
            }
            #pragma unroll
            for (int ni = 0; ni < 4; ni++) {
                const int n = (wn << 5) + (ni << 3) + lr;
                bf[ni][0] = Ws[n * GSTRIDE + kc];
                bf[ni][1] = Ws[n * GSTRIDE + kc + 4];
            }
            #pragma unroll
            for (int mi = 0; mi < 4; mi++)
                #pragma unroll
                for (int ni = 0; ni < 4; ni++)
                    mma_tf32(acc[mi][ni][0], acc[mi][ni][1],
                             acc[mi][ni][2], acc[mi][ni][3],
                             af[mi][0], af[mi][1], af[mi][2], af[mi][3],
                             bf[ni][0], bf[ni][1]);
        }
        __syncthreads();
        if (i + GSTAGES < niter)
            g_load_stage(sb, A, W, K, bm, bn, buf, i + GSTAGES, tid);
        else
            CPCOMMIT();
    }

    // epilogue: direct fragment stores + bias
    #pragma unroll
    for (int mi = 0; mi < 4; mi++) {
        const int row = bm + (wm << 6) + (mi << 4) + lr;
        #pragma unroll
        for (int ni = 0; ni < 4; ni++) {
            const int col = bn + (wn << 5) + (ni << 3) + (lq << 1);
            const float b0 = bias[col], b1 = bias[col + 1];
            float2 o0 = make_float2(acc[mi][ni][0] + b0, acc[mi][ni][1] + b1);
            float2 o1 = make_float2(acc[mi][ni][2] + b0, acc[mi][ni][3] + b1);
            *(float2*)&C[(size_t)row * N + col] = o0;
            *(float2*)&C[(size_t)(row + 8) * N + col] = o1;
        }
    }
}

// ---------------------------------------------------------------------------
// tf32 rounding prep
// ---------------------------------------------------------------------------
__global__ void round_tf32_kernel(const float4* __restrict__ in,
                                  float4* __restrict__ out, int n4)
{
    int i = blockIdx.x * blockDim.x + threadIdx.x;
    if (i < n4) {
        float4 v = in[i];
        v.x = tf32r(v.x); v.y = tf32r(v.y); v.z = tf32r(v.z); v.w = tf32r(v.w);
        out[i] = v;
    }
}

// ---------------------------------------------------------------------------
// RoPE + split/transpose: qkv[B,S,3,H,HD] -> q,k (rotated), v in [B,H,S,HD]
// ---------------------------------------------------------------------------
__global__ void rope_split_kernel(const float* __restrict__ qkv,
                                  const float* __restrict__ freqs,
                                  float* __restrict__ q,
                                  float* __restrict__ k,
                                  float* __restrict__ v)
{
    const int idx = blockIdx.x * blockDim.x + threadIdx.x;
    const int i = idx & 31;
    const int h = (idx >> 5) & 15;
    const int s = (idx >> 9) & 2047;
    const int b = idx >> 20;

    const float f = freqs[s * 32 + i];
    const float c  = cosf(f);
    const float sn = sinf(f);

    const float* base = qkv + (size_t)(b * SS + s) * NQKV + h * HDD + 2 * i;
    const float q0 = base[0],      q1 = base[1];
    const float k0 = base[DD],     k1 = base[DD + 1];
    const float v0 = base[2 * DD], v1 = base[2 * DD + 1];

    const size_t o = ((size_t)((b * HH + h) * SS) + s) * HDD + 2 * i;
    q[o]     = q0 * c - q1 * sn;
    q[o + 1] = q0 * sn + q1 * c;
    k[o]     = k0 * c - k1 * sn;
    k[o + 1] = k0 * sn + k1 * c;
    v[o]     = v0;
    v[o + 1] = v1;
}

// ---------------------------------------------------------------------------
// Flash attention with tf32 mma.sync. BQ=BK=64, HD=64, 128 thr (4 warps),
// each warp owns 16 q-rows. Online softmax in fp32.
// smem: Qs[64][68], Ks[64][68], Ps[64][68] (stride%32==4: conflict-free
// A/B frag LDS), Vs[64][72] (stride%32==8: conflict-free k-major B frags).
// ---------------------------------------------------------------------------
#define QS_STR 68
#define VS_STR 72
#define FA_QS 0
#define FA_KS (64 * QS_STR)
#define FA_PS (2 * 64 * QS_STR)
#define FA_VS (3 * 64 * QS_STR)
#define FA_SMEM ((3 * 64 * QS_STR + 64 * VS_STR) * 4)   // 70656 bytes

__global__ void __launch_bounds__(128) flash_mma_kernel(
    const float* __restrict__ Q, const float* __restrict__ K,
    const float* __restrict__ V, float* __restrict__ O)
{
    extern __shared__ float sm[];
    float* Qs = sm + FA_QS;
    float* Ks = sm + FA_KS;
    float* Ps = sm + FA_PS;
    float* Vs = sm + FA_VS;
    const uint32_t* Qu = (const uint32_t*)Qs;
    const uint32_t* Ku = (const uint32_t*)Ks;
    const uint32_t* Pu = (const uint32_t*)Ps;
    const uint32_t* Vu = (const uint32_t*)Vs;

    const int tid  = threadIdx.x;
    const int lane = tid & 31;
    const int wid  = tid >> 5;      // 0..3
    const int lr   = lane >> 2;     // 0..7
    const int lq   = lane & 3;      // 0..3
    const int wm   = wid << 4;      // warp q-row base (0,16,32,48)
    const int q0   = blockIdx.x << 6;
    const int bh   = blockIdx.y;

    const float* Qb = Q + ((size_t)bh * SS + q0) * HDD;
    const float* Kb = K + (size_t)bh * SS * HDD;
    const float* Vb = V + (size_t)bh * SS * HDD;

    // load Q (scaled by 1/sqrt(HD), tf32-rounded)
    #pragma unroll
    for (int i = 0; i < 8; i++) {
        int idx = tid + (i << 7);           // 0..1023 chunks of 4
        int r = idx >> 4, c = (idx & 15) << 2;
        float4 t = *(const float4*)(Qb + r * HDD + c);
        Qs[r * QS_STR + c + 0] = tf32r(t.x * 0.125f);
        Qs[r * QS_STR + c + 1] = tf32r(t.y * 0.125f);
        Qs[r * QS_STR + c + 2] = tf32r(t.z * 0.125f);
        Qs[r * QS_STR + c + 3] = tf32r(t.w * 0.125f);
    }

    float mrow[2], lrow[2], oacc[8][4];
    mrow[0] = mrow[1] = -1e30f;
    lrow[0] = lrow[1] = 0.f;
    #pragma unroll
    for (int j = 0; j < 8; j++)
        #pragma unroll
        for (int e = 0; e < 4; e++) oacc[j][e] = 0.f;

    const int ntiles = (q0 >> 6) + 1;
    for (int t = 0; t < ntiles; t++) {
        const int k0 = t << 6;
        __syncthreads();    // prior tile's Ks/Vs reads complete
        #pragma unroll
        for (int i = 0; i < 8; i++) {
            int idx = tid + (i << 7);
            int r = idx >> 4, c = (idx & 15) << 2;
            float4 kt = *(const float4*)(Kb + (size_t)(k0 + r) * HDD + c);
            Ks[r * QS_STR + c + 0] = tf32r(kt.x);
            Ks[r * QS_STR + c + 1] = tf32r(kt.y);
            Ks[r * QS_STR + c + 2] = tf32r(kt.z);
            Ks[r * QS_STR + c + 3] = tf32r(kt.w);
            float4 vt = *(const float4*)(Vb + (size_t)(k0 + r) * HDD + c);
            Vs[r * VS_STR + c + 0] = tf32r(vt.x);
            Vs[r * VS_STR + c + 1] = tf32r(vt.y);
            Vs[r * VS_STR + c + 2] = tf32r(vt.z);
            Vs[r * VS_STR + c + 3] = tf32r(vt.w);
        }
        __syncthreads();

        // S = Q K^T   (warp: m16 x n64, k64)
        float sc[8][4];
        #pragma unroll
        for (int j = 0; j < 8; j++)
            #pragma unroll
            for (int e = 0; e < 4; e++) sc[j][e] = 0.f;
        #pragma unroll
        for (int ks = 0; ks < 8; ks++) {
            const int kc = (ks << 3) + lq;
            const int ar = wm + lr;
            uint32_t a0 = Qu[ar * QS_STR + kc];
            uint32_t a1 = Qu[(ar + 8) * QS_STR + kc];
            uint32_t a2 = Qu[ar * QS_STR + kc + 4];
            uint32_t a3 = Qu[(ar + 8) * QS_STR + kc + 4];
            #pragma unroll
            for (int j = 0; j < 8; j++) {
                const int n = (j << 3) + lr;
                uint32_t b0 = Ku[n * QS_STR + kc];
                uint32_t b1 = Ku[n * QS_STR + kc + 4];
                mma_tf32(sc[j][0], sc[j][1], sc[j][2], sc[j][3],
                         a0, a1, a2, a3, b0, b1);
            }
        }

        // causal mask (diagonal tile only): local col > local row
        if (k0 == q0) {
            #pragma unroll
            for (int j = 0; j < 8; j++) {
                const int c0 = (j << 3) + (lq << 1);
                const int r0 = wm + lr;
                if (c0 > r0)         sc[j][0] = -1e30f;
                if (c0 + 1 > r0)     sc[j][1] = -1e30f;
                if (c0 > r0 + 8)     sc[j][2] = -1e30f;
                if (c0 + 1 > r0 + 8) sc[j][3] = -1e30f;
            }
        }

        __syncwarp();   // prior PV reads of Ps done before overwrite

        // online softmax (two row-halves: lr and lr+8)
        #pragma unroll
        for (int h = 0; h < 2; h++) {
            float vmax = -1e30f;
            #pragma unroll
            for (int j = 0; j < 8; j++)
                vmax = fmaxf(vmax, fmaxf(sc[j][2 * h], sc[j][2 * h + 1]));
            vmax = fmaxf(vmax, __shfl_xor_sync(0xffffffffu, vmax, 1));
            vmax = fmaxf(vmax, __shfl_xor_sync(0xffffffffu, vmax, 2));
            const float mnew = fmaxf(mrow[h], vmax);
            const float corr = __expf(mrow[h] - mnew);
            mrow[h] = mnew;
            float rs = 0.f;
            #pragma unroll
            for (int j = 0; j < 8; j++) {
                float e0 = __expf(sc[j][2 * h] - mnew);
                float e1 = __expf(sc[j][2 * h + 1] - mnew);
                rs += e0 + e1;
                oacc[j][2 * h] *= corr;
                oacc[j][2 * h + 1] *= corr;
                *(float2*)&Ps[(wm + lr + 8 * h) * QS_STR + (j << 3) + (lq << 1)] =
                    make_float2(tf32r(e0), tf32r(e1));
            }
            rs += __shfl_xor_sync(0xffffffffu, rs, 1);
            rs += __shfl_xor_sync(0xffffffffu, rs, 2);
            lrow[h] = lrow[h] * corr + rs;
        }
        __syncwarp();

        // O += P @ V   (warp: m16 x n64, k64)
        #pragma unroll
        for (int ks = 0; ks < 8; ks++) {
            const int kc = (ks << 3) + lq;
            const int ar = wm + lr;
            uint32_t a0 = Pu[ar * QS_STR + kc];
            uint32_t a1 = Pu[(ar + 8) * QS_STR + kc];
            uint32_t a2 = Pu[ar * QS_STR + kc + 4];
            uint32_t a3 = Pu[(ar + 8) * QS_STR + kc + 4];
            #pragma unroll
            for (int j = 0; j < 8; j++) {
                const int n = (j << 3) + lr;
                uint32_t b0 = Vu[kc * VS_STR + n];
                uint32_t b1 = Vu[(kc + 4) * VS_STR + n];
                mma_tf32(oacc[j][0], oacc[j][1], oacc[j][2], oacc[j][3],
                         a0, a1, a2, a3, b0, b1);
            }
        }
    }

    // epilogue: normalize, write [B,S,D] (tf32-rounded for the proj GEMM)
    const int b = bh >> 4;
    const int h = bh & 15;
    float* Ob = O + ((size_t)(b * SS + q0)) * DD + h * HDD;
    const float inv0 = 1.f / lrow[0];
    const float inv1 = 1.f / lrow[1];
    #pragma unroll
    for (int j = 0; j < 8; j++) {
        const int col = (j << 3) + (lq << 1);
        const int row = wm + lr;
        *(float2*)&Ob[(size_t)row * DD + col] =
            make_float2(tf32r(oacc[j][0] * inv0), tf32r(oacc[j][1] * inv0));
        *(float2*)&Ob[(size_t)(row + 8) * DD + col] =
            make_float2(tf32r(oacc[j][2] * inv1), tf32r(oacc[j][3] * inv1));
    }
}

// ---------------------------------------------------------------------------
// Launch
// ---------------------------------------------------------------------------
extern "C" void kernel_launch(void* const* d_in, const int* in_sizes, int n_in,
                              void* d_out, int out_size)
{
    const float* x      = (const float*)d_in[0];
    // d_in[1] = attn_mask (bool tril) — causal, handled analytically
    const float* freqs  = (const float*)d_in[2];
    const float* w_qkv  = (const float*)d_in[3];
    const float* b_qkv  = (const float*)d_in[4];
    const float* w_proj = (const float*)d_in[5];
    const float* b_proj = (const float*)d_in[6];
    float* out = (float*)d_out;

    float *qkv_p, *q_p, *k_p, *v_p, *attn_p, *xr_p, *wqkvr_p, *wprojr_p;
    cudaGetSymbolAddress((void**)&qkv_p,    g_qkv);
    cudaGetSymbolAddress((void**)&q_p,      g_q);
    cudaGetSymbolAddress((void**)&k_p,      g_k);
    cudaGetSymbolAddress((void**)&v_p,      g_v);
    cudaGetSymbolAddress((void**)&attn_p,   g_attn);
    cudaGetSymbolAddress((void**)&xr_p,     g_xr);
    cudaGetSymbolAddress((void**)&wqkvr_p,  g_wqkvr);
    cudaGetSymbolAddress((void**)&wprojr_p, g_wprojr);

    cudaFuncSetAttribute(gemm_mma_tf32,
                         cudaFuncAttributeMaxDynamicSharedMemorySize, GEMM_SMEM);
    cudaFuncSetAttribute(flash_mma_kernel,
                         cudaFuncAttributeMaxDynamicSharedMemorySize, FA_SMEM);

    // 0) tf32-round GEMM operands
    round_tf32_kernel<<<(MTOT * DD / 4 + 255) / 256, 256>>>(
        (const float4*)x, (float4*)xr_p, MTOT * DD / 4);
    round_tf32_kernel<<<(NQKV * DD / 4 + 255) / 256, 256>>>(
        (const float4*)w_qkv, (float4*)wqkvr_p, NQKV * DD / 4);
    round_tf32_kernel<<<(DD * DD / 4 + 255) / 256, 256>>>(
        (const float4*)w_proj, (float4*)wprojr_p, DD * DD / 4);

    // 1) QKV = x @ w_qkv^T + b_qkv (tensor-core tf32)
    gemm_mma_tf32<<<dim3(NQKV / 128, MTOT / 128), 256, GEMM_SMEM>>>(
        xr_p, wqkvr_p, b_qkv, qkv_p, MTOT, NQKV, DD);

    // 2) RoPE + split into [B,H,S,HD]
    rope_split_kernel<<<(BB * SS * HH * (HDD / 2)) / 256, 256>>>(
        qkv_p, freqs, q_p, k_p, v_p);

    // 3) Causal flash attention (tensor-core tf32) -> [B,S,D]
    flash_mma_kernel<<<dim3(SS / 64, BB * HH), 128, FA_SMEM>>>(
        q_p, k_p, v_p, attn_p);

    // 4) out = attn @ w_proj^T + b_proj (tensor-core tf32)
    gemm_mma_tf32<<<dim3(DD / 128, MTOT / 128), 256, GEMM_SMEM>>>(
        attn_p, wprojr_p, b_proj, out, MTOT, DD, DD);
}

// round 4
// speedup vs baseline: 3.7576x; 1.2456x over previous
#include <cuda_runtime.h>
#include <cstdint>
#include <math.h>

#define BB 2
#define SS 2048
#define DD 1024
#define HH 16
#define HDD 64
#define MTOT (BB * SS)      // 4096
#define NQKV (3 * DD)       // 3072

// ---------------- device scratch (no allocation allowed) -------------------
__device__ float g_q[BB * HH * SS * HDD];   // 16 MB, tf32-rounded, 0.125-scaled
__device__ float g_k[BB * HH * SS * HDD];   // tf32-rounded
__device__ float g_v[BB * HH * SS * HDD];   // tf32-rounded
__device__ float g_attn[MTOT * DD];         // flash out, tf32-rounded
__device__ float g_xr[MTOT * DD];           // tf32-rounded x
__device__ float g_wqkvr[NQKV * DD];        // tf32-rounded w_qkv
__device__ float g_wprojr[DD * DD];         // tf32-rounded w_proj
__device__ float2 g_cs[SS * (HDD / 2)];     // cos/sin table

// ---------------- helpers ---------------------------------------------------
__device__ __forceinline__ uint32_t smem_u32(const void* p) {
    uint32_t a;
    asm("{ .reg .u64 t; cvta.to.shared.u64 t, %1; cvt.u32.u64 %0, t; }"
        : "=r"(a) : "l"(p));
    return a;
}
__device__ __forceinline__ float tf32r(float x) {
    float y;
    asm("cvt.rna.tf32.f32 %0, %1;" : "=f"(y) : "f"(x));
    return y;
}
__device__ __forceinline__ void mma_tf32(
    float& c0, float& c1, float& c2, float& c3,
    uint32_t a0, uint32_t a1, uint32_t a2, uint32_t a3,
    uint32_t b0, uint32_t b1)
{
    asm volatile(
        "mma.sync.aligned.m16n8k8.row.col.f32.tf32.tf32.f32 "
        "{%0,%1,%2,%3}, {%4,%5,%6,%7}, {%8,%9}, {%0,%1,%2,%3};"
        : "+f"(c0), "+f"(c1), "+f"(c2), "+f"(c3)
        : "r"(a0), "r"(a1), "r"(a2), "r"(a3), "r"(b0), "r"(b1));
}
#define CPASYNC16(dst, src) \
    asm volatile("cp.async.cg.shared.global [%0], [%1], 16;" :: "r"(dst), "l"(src))
#define CPCOMMIT() asm volatile("cp.async.commit_group;")

// ---------------------------------------------------------------------------
// tf32 mma.sync GEMM mainloop infrastructure.
// 128x128 CTA tile, 256 thr (8 warps: 2x4, 64x32 warp tiles), BK=32,
// 3-stage cp.async, XOR-swizzled pad-free smem (16KB/operand/stage).
// Layout: float (r, c) at r*32 + (((c>>2) ^ (r&7))<<2) + (c&3).
// All fragment rows satisfy row%8 == lr, so the XOR term is just lr.
// ---------------------------------------------------------------------------
#define GSTAGES 3
#define GTILE_B 16384                        // 128*32*4
#define GSTAGE_B (2 * GTILE_B)               // 32768
#define GEMM_SMEM (GSTAGES * GSTAGE_B)       // 98304 -> 2 CTAs/SM

__device__ __forceinline__ void g_load_stage(
    uint32_t sbase, const float* A, const float* W, int K,
    int bm, int bn, int buf, int it, int tid)
{
    uint32_t sa = sbase + buf * GSTAGE_B;
    uint32_t sw = sa + GTILE_B;
    const float* Ag = A + (size_t)bm * K + it * 32;
    const float* Wg = W + (size_t)bn * K + it * 32;
    #pragma unroll
    for (int i = 0; i < 4; i++) {
        int idx = tid + (i << 8);            // 0..1023
        int row = idx >> 3, cc = idx & 7;
        uint32_t off = (row * 32 + ((cc ^ (row & 7)) << 2)) * 4;
        CPASYNC16(sa + off, Ag + (size_t)row * K + (cc << 2));
        CPASYNC16(sw + off, Wg + (size_t)row * K + (cc << 2));
    }
    CPCOMMIT();
}

// Mainloop producing acc[4][4][4]; shared by both GEMM kernels.
#define GEMM_MAINLOOP(A_, W_, K_)                                              \
    float acc[4][4][4];                                                        \
    _Pragma("unroll") for (int mi = 0; mi < 4; mi++)                           \
        _Pragma("unroll") for (int ni = 0; ni < 4; ni++)                       \
            _Pragma("unroll") for (int e = 0; e < 4; e++) acc[mi][ni][e] = 0.f;\
    const int niter = (K_) >> 5;                                               \
    for (int s = 0; s < GSTAGES; s++)                                          \
        g_load_stage(sb, A_, W_, K_, bm, bn, s, s, tid);                       \
    for (int i = 0; i < niter; i++) {                                          \
        const int buf = i % GSTAGES;                                           \
        asm volatile("cp.async.wait_group 2;" ::: "memory");                   \
        __syncthreads();                                                       \
        const uint32_t* As = (const uint32_t*)(smem + buf * GSTAGE_B);         \
        const uint32_t* Ws = (const uint32_t*)(smem + buf * GSTAGE_B + GTILE_B);\
        _Pragma("unroll")                                                      \
        for (int ks = 0; ks < 4; ks++) {                                       \
            const int c0 = (((ks << 1) ^ lr) << 2) + lq;                       \
            const int c1 = ((((ks << 1) | 1) ^ lr) << 2) + lq;                 \
            uint32_t af[4][4], bf[4][2];                                       \
            _Pragma("unroll") for (int mi = 0; mi < 4; mi++) {                 \
                const int r = (wm << 6) + (mi << 4) + lr;                      \
                af[mi][0] = As[r * 32 + c0];                                   \
                af[mi][1] = As[(r + 8) * 32 + c0];                             \
                af[mi][2] = As[r * 32 + c1];                                   \
                af[mi][3] = As[(r + 8) * 32 + c1];                             \
            }                                                                  \
            _Pragma("unroll") for (int ni = 0; ni < 4; ni++) {                 \
                const int n = (wn << 5) + (ni << 3) + lr;                      \
                bf[ni][0] = Ws[n * 32 + c0];                                   \
                bf[ni][1] = Ws[n * 32 + c1];                                   \
            }                                                                  \
            _Pragma("unroll") for (int mi = 0; mi < 4; mi++)                   \
                _Pragma("unroll") for (int ni = 0; ni < 4; ni++)               \
                    mma_tf32(acc[mi][ni][0], acc[mi][ni][1],                   \
                             acc[mi][ni][2], acc[mi][ni][3],                   \
                             af[mi][0], af[mi][1], af[mi][2], af[mi][3],       \
                             bf[ni][0], bf[ni][1]);                            \
        }                                                                      \
        __syncthreads();                                                       \
        if (i + GSTAGES < niter)                                               \
            g_load_stage(sb, A_, W_, K_, bm, bn, buf, i + GSTAGES, tid);       \
        else                                                                   \
            CPCOMMIT();                                                        \
    }

// ---------------------------------------------------------------------------
// Generic GEMM (proj): C = A @ W^T + bias
// ---------------------------------------------------------------------------
__global__ void __launch_bounds__(256, 2) gemm_mma_tf32(
    const float* __restrict__ A, const float* __restrict__ W,
    const float* __restrict__ bias, float* __restrict__ C,
    int M, int N, int K)
{
    extern __shared__ char smem[];
    uint32_t sb = smem_u32(smem);
    const int tid  = threadIdx.x;
    const int lane = tid & 31;
    const int wid  = tid >> 5;
    const int wm   = wid >> 2, wn = wid & 3;
    const int bm = blockIdx.y << 7, bn = blockIdx.x << 7;
    const int lr = lane >> 2, lq = lane & 3;

    GEMM_MAINLOOP(A, W, K)

    #pragma unroll
    for (int mi = 0; mi < 4; mi++) {
        const int row = bm + (wm << 6) + (mi << 4) + lr;
        #pragma unroll
        for (int ni = 0; ni < 4; ni++) {
            const int col = bn + (wn << 5) + (ni << 3) + (lq << 1);
            const float b0 = bias[col], b1 = bias[col + 1];
            *(float2*)&C[(size_t)row * N + col] =
                make_float2(acc[mi][ni][0] + b0, acc[mi][ni][1] + b1);
            *(float2*)&C[(size_t)(row + 8) * N + col] =
                make_float2(acc[mi][ni][2] + b0, acc[mi][ni][3] + b1);
        }
    }
}

// ---------------------------------------------------------------------------
// QKV GEMM with fused RoPE epilogue. N = 3072; each 128-col block lies
// entirely in one of the q/k/v sections. Writes q (rotated, *0.125),
// k (rotated), v — all tf32-rounded, [B,H,S,HD] layout.
// ---------------------------------------------------------------------------
__global__ void __launch_bounds__(256, 2) gemm_qkv_rope(
    const float* __restrict__ A, const float* __restrict__ W,
    const float* __restrict__ bias, const float2* __restrict__ cs,
    float* __restrict__ qo, float* __restrict__ ko, float* __restrict__ vo,
    int K)
{
    extern __shared__ char smem[];
    uint32_t sb = smem_u32(smem);
    const int tid  = threadIdx.x;
    const int lane = tid & 31;
    const int wid  = tid >> 5;
    const int wm   = wid >> 2, wn = wid & 3;
    const int bm = blockIdx.y << 7, bn = blockIdx.x << 7;
    const int lr = lane >> 2, lq = lane & 3;

    GEMM_MAINLOOP(A, W, K)

    const int sec = bn >> 10;   // 0=q, 1=k, 2=v (uniform per CTA)
    #pragma unroll
    for (int mi = 0; mi < 4; mi++) {
        #pragma unroll
        for (int ni = 0; ni < 4; ni++) {
            const int col = bn + (wn << 5) + (ni << 3) + (lq << 1);
            const int h   = (col >> 6) & 15;
            const int d2  = (col & 63) >> 1;
            const float b0 = bias[col], b1 = bias[col + 1];
            #pragma unroll
            for (int hf = 0; hf < 2; hf++) {
                const int row = bm + (wm << 6) + (mi << 4) + lr + (hf << 3);
                const int b = row >> 11, s = row & 2047;
                const float v0 = acc[mi][ni][2 * hf]     + b0;
                const float v1 = acc[mi][ni][2 * hf + 1] + b1;
                const size_t o =
                    ((size_t)((b * HH + h) * SS + s)) * HDD + (d2 << 1);
                if (sec == 2) {
                    *(float2*)&vo[o] = make_float2(tf32r(v0), tf32r(v1));
                } else {
                    const float2 t = cs[s * 32 + d2];
                    float r0 = v0 * t.x - v1 * t.y;
                    float r1 = v0 * t.y + v1 * t.x;
                    if (sec == 0) {
                        *(float2*)&qo[o] = make_float2(tf32r(r0 * 0.125f),
                                                       tf32r(r1 * 0.125f));
                    } else {
                        *(float2*)&ko[o] = make_float2(tf32r(r0), tf32r(r1));
                    }
                }
            }
        }
    }
}

// ---------------------------------------------------------------------------
// prep kernels
// ---------------------------------------------------------------------------
__global__ void round_tf32_kernel(const float4* __restrict__ in,
                                  float4* __restrict__ out, int n4)
{
    int i = blockIdx.x * blockDim.x + threadIdx.x;
    if (i < n4) {
        float4 v = in[i];
        v.x = tf32r(v.x); v.y = tf32r(v.y); v.z = tf32r(v.z); v.w = tf32r(v.w);
        out[i] = v;
    }
}

__global__ void cs_table_kernel(const float* __restrict__ freqs,
                                float2* __restrict__ cs, int n)
{
    int i = blockIdx.x * blockDim.x + threadIdx.x;
    if (i < n) {
        float f = freqs[i];
        cs[i] = make_float2(cosf(f), sinf(f));
    }
}

// ---------------------------------------------------------------------------
// Flash attention, tf32 mma.sync, cp.async double-buffered K/V.
// BQ=BK=64, HD=64, 128 thr (4 warps x 16 q-rows). q/k/v arrive pre-rounded
// (q pre-scaled). Online softmax fp32.
// ---------------------------------------------------------------------------
#define QS_STR 68
#define VS_STR 72
#define FA_QS 0
#define FA_PS (64 * QS_STR)
#define FA_K0 (2 * 64 * QS_STR)            // stage b: FA_K0 + b*64*QS_STR
#define FA_V0 (4 * 64 * QS_STR)            // stage b: FA_V0 + b*64*VS_STR
#define FA_SMEM ((4 * 64 * QS_STR + 2 * 64 * VS_STR) * 4)   // 106496 bytes

__device__ __forceinline__ void fa_load_kv(
    uint32_t sbq, const float* Kb, const float* Vb, int k0, int buf, int tid)
{
    uint32_t ks = sbq + (FA_K0 + buf * 64 * QS_STR) * 4;
    uint32_t vs = sbq + (FA_V0 + buf * 64 * VS_STR) * 4;
    #pragma unroll
    for (int i = 0; i < 8; i++) {
        int idx = tid + (i << 7);          // 0..1023
        int r = idx >> 4, c4 = (idx & 15) << 2;
        CPASYNC16(ks + (r * QS_STR + c4) * 4, Kb + (size_t)(k0 + r) * HDD + c4);
        CPASYNC16(vs + (r * VS_STR + c4) * 4, Vb + (size_t)(k0 + r) * HDD + c4);
    }
    CPCOMMIT();
}

__global__ void __launch_bounds__(128) flash_mma_kernel(
    const float* __restrict__ Q, const float* __restrict__ K,
    const float* __restrict__ V, float* __restrict__ O)
{
    extern __shared__ float sm[];
    uint32_t sbq = smem_u32(sm);
    float* Qs = sm + FA_QS;
    float* Ps = sm + FA_PS;
    const uint32_t* Qu = (const uint32_t*)Qs;
    const uint32_t* Pu = (const uint32_t*)Ps;

    const int tid  = threadIdx.x;
    const int lane = tid & 31;
    const int wid  = tid >> 5;
    const int lr   = lane >> 2, lq = lane & 3;
    const int wm   = wid << 4;
    const int q0   = blockIdx.x << 6;
    const int bh   = blockIdx.y;

    const float* Qb = Q + ((size_t)bh * SS + q0) * HDD;
    const float* Kb = K + (size_t)bh * SS * HDD;
    const float* Vb = V + (size_t)bh * SS * HDD;

    const int ntiles = (q0 >> 6) + 1;
    fa_load_kv(sbq, Kb, Vb, 0, 0, tid);

    // Q tile (already rounded+scaled)
    #pragma unroll
    for (int i = 0; i < 8; i++) {
        int idx = tid + (i << 7);
        int r = idx >> 4, c4 = (idx & 15) << 2;
        float4 t = *(const float4*)(Qb + r * HDD + c4);
        *(float4*)&Qs[r * QS_STR + c4] = t;
    }

    float mrow[2], lrow[2], oacc[8][4];
    mrow[0] = mrow[1] = -1e30f;
    lrow[0] = lrow[1] = 0.f;
    #pragma unroll
    for (int j = 0; j < 8; j++)
        #pragma unroll
        for (int e = 0; e < 4; e++) oacc[j][e] = 0.f;

    for (int t = 0; t < ntiles; t++) {
        if (t + 1 < ntiles) {
            fa_load_kv(sbq, Kb, Vb, (t + 1) << 6, (t + 1) & 1, tid);
            asm volatile("cp.async.wait_group 1;" ::: "memory");
        } else {
            asm volatile("cp.async.wait_group 0;" ::: "memory");
        }
        __syncthreads();

        const uint32_t* Ku = (const uint32_t*)(sm + FA_K0 + (t & 1) * 64 * QS_STR);
        const uint32_t* Vu = (const uint32_t*)(sm + FA_V0 + (t & 1) * 64 * VS_STR);

        // S = Q K^T   (warp: m16 x n64, k64)
        float sc[8][4];
        #pragma unroll
        for (int j = 0; j < 8; j++)
            #pragma unroll
            for (int e = 0; e < 4; e++) sc[j][e] = 0.f;
        #pragma unroll
        for (int ks = 0; ks < 8; ks++) {
            const int kc = (ks << 3) + lq;
            const int ar = wm + lr;
            uint32_t a0 = Qu[ar * QS_STR + kc];
            uint32_t a1 = Qu[(ar + 8) * QS_STR + kc];
            uint32_t a2 = Qu[ar * QS_STR + kc + 4];
            uint32_t a3 = Qu[(ar + 8) * QS_STR + kc + 4];
            #pragma unroll
            for (int j = 0; j < 8; j++) {
                const int n = (j << 3) + lr;
                mma_tf32(sc[j][0], sc[j][1], sc[j][2], sc[j][3],
                         a0, a1, a2, a3,
                         Ku[n * QS_STR + kc], Ku[n * QS_STR + kc + 4]);
            }
        }

        if ((t << 6) == q0) {   // diagonal tile: causal mask
            #pragma unroll
            for (int j = 0; j < 8; j++) {
                const int c0 = (j << 3) + (lq << 1);
                const int r0 = wm + lr;
                if (c0 > r0)         sc[j][0] = -1e30f;
                if (c0 + 1 > r0)     sc[j][1] = -1e30f;
                if (c0 > r0 + 8)     sc[j][2] = -1e30f;
                if (c0 + 1 > r0 + 8) sc[j][3] = -1e30f;
            }
        }

        __syncwarp();   // prior PV reads of Ps complete (warp-private rows)

        #pragma unroll
        for (int h = 0; h < 2; h++) {
            float vmax = -1e30f;
            #pragma unroll
            for (int j = 0; j < 8; j++)
                vmax = fmaxf(vmax, fmaxf(sc[j][2 * h], sc[j][2 * h + 1]));
            vmax = fmaxf(vmax, __shfl_xor_sync(0xffffffffu, vmax, 1));
            vmax = fmaxf(vmax, __shfl_xor_sync(0xffffffffu, vmax, 2));
            const float mnew = fmaxf(mrow[h], vmax);
            const float corr = __expf(mrow[h] - mnew);
            mrow[h] = mnew;
            float rs = 0.f;
            #pragma unroll
            for (int j = 0; j < 8; j++) {
                float e0 = __expf(sc[j][2 * h] - mnew);
                float e1 = __expf(sc[j][2 * h + 1] - mnew);
                rs += e0 + e1;
                oacc[j][2 * h] *= corr;
                oacc[j][2 * h + 1] *= corr;
                *(float2*)&Ps[(wm + lr + 8 * h) * QS_STR + (j << 3) + (lq << 1)] =
                    make_float2(tf32r(e0), tf32r(e1));
            }
            rs += __shfl_xor_sync(0xffffffffu, rs, 1);
            rs += __shfl_xor_sync(0xffffffffu, rs, 2);
            lrow[h] = lrow[h] * corr + rs;
        }
        __syncwarp();

        // O += P @ V
        #pragma unroll
        for (int ks = 0; ks < 8; ks++) {
            const int kc = (ks << 3) + lq;
            const int ar = wm + lr;
            uint32_t a0 = Pu[ar * QS_STR + kc];
            uint32_t a1 = Pu[(ar + 8) * QS_STR + kc];
            uint32_t a2 = Pu[ar * QS_STR + kc + 4];
            uint32_t a3 = Pu[(ar + 8) * QS_STR + kc + 4];
            #pragma unroll
            for (int j = 0; j < 8; j++) {
                const int n = (j << 3) + lr;
                mma_tf32(oacc[j][0], oacc[j][1], oacc[j][2], oacc[j][3],
                         a0, a1, a2, a3,
                         Vu[kc * VS_STR + n], Vu[(kc + 4) * VS_STR + n]);
            }
        }
        __syncthreads();   // Ks/Vs buf reads done before overwrite next iter
    }

    const int b = bh >> 4;
    const int h = bh & 15;
    float* Ob = O + ((size_t)(b * SS + q0)) * DD + h * HDD;
    const float inv0 = 1.f / lrow[0];
    const float inv1 = 1.f / lrow[1];
    #pragma unroll
    for (int j = 0; j < 8; j++) {
        const int col = (j << 3) + (lq << 1);
        const int row = wm + lr;
        *(float2*)&Ob[(size_t)row * DD + col] =
            make_float2(tf32r(oacc[j][0] * inv0), tf32r(oacc[j][1] * inv0));
        *(float2*)&Ob[(size_t)(row + 8) * DD + col] =
            make_float2(tf32r(oacc[j][2] * inv1), tf32r(oacc[j][3] * inv1));
    }
}

// ---------------------------------------------------------------------------
// Launch
// ---------------------------------------------------------------------------
extern "C" void kernel_launch(void* const* d_in, const int* in_sizes, int n_in,
                              void* d_out, int out_size)
{
    const float* x      = (const float*)d_in[0];
    // d_in[1] = attn_mask (bool tril) — causal, handled analytically
    const float* freqs  = (const float*)d_in[2];
    const float* w_qkv  = (const float*)d_in[3];
    const float* b_qkv  = (const float*)d_in[4];
    const float* w_proj = (const float*)d_in[5];
    const float* b_proj = (const float*)d_in[6];
    float* out = (float*)d_out;

    float *q_p, *k_p, *v_p, *attn_p, *xr_p, *wqkvr_p, *wprojr_p;
    float2* cs_p;
    cudaGetSymbolAddress((void**)&q_p,      g_q);
    cudaGetSymbolAddress((void**)&k_p,      g_k);
    cudaGetSymbolAddress((void**)&v_p,      g_v);
    cudaGetSymbolAddress((void**)&attn_p,   g_attn);
    cudaGetSymbolAddress((void**)&xr_p,     g_xr);
    cudaGetSymbolAddress((void**)&wqkvr_p,  g_wqkvr);
    cudaGetSymbolAddress((void**)&wprojr_p, g_wprojr);
    cudaGetSymbolAddress((void**)&cs_p,     g_cs);

    cudaFuncSetAttribute(gemm_mma_tf32,
                         cudaFuncAttributeMaxDynamicSharedMemorySize, GEMM_SMEM);
    cudaFuncSetAttribute(gemm_qkv_rope,
                         cudaFuncAttributeMaxDynamicSharedMemorySize, GEMM_SMEM);
    cudaFuncSetAttribute(flash_mma_kernel,
                         cudaFuncAttributeMaxDynamicSharedMemorySize, FA_SMEM);

    // 0) prep: tf32-round operands, cos/sin table
    round_tf32_kernel<<<(MTOT * DD / 4 + 255) / 256, 256>>>(
        (const float4*)x, (float4*)xr_p, MTOT * DD / 4);
    round_tf32_kernel<<<(NQKV * DD / 4 + 255) / 256, 256>>>(
        (const float4*)w_qkv, (float4*)wqkvr_p, NQKV * DD / 4);
    round_tf32_kernel<<<(DD * DD / 4 + 255) / 256, 256>>>(
        (const float4*)w_proj, (float4*)wprojr_p, DD * DD / 4);
    cs_table_kernel<<<(SS * 32 + 255) / 256, 256>>>(freqs, cs_p, SS * 32);

    // 1) QKV GEMM + fused RoPE/split -> q,k,v in [B,H,S,HD]
    gemm_qkv_rope<<<dim3(NQKV / 128, MTOT / 128), 256, GEMM_SMEM>>>(
        xr_p, wqkvr_p, b_qkv, cs_p, q_p, k_p, v_p, DD);

    // 2) Causal flash attention (tensor-core tf32) -> [B,S,D]
    flash_mma_kernel<<<dim3(SS / 64, BB * HH), 128, FA_SMEM>>>(
        q_p, k_p, v_p, attn_p);

    // 3) out = attn @ w_proj^T + b_proj
    gemm_mma_tf32<<<dim3(DD / 128, MTOT / 128), 256, GEMM_SMEM>>>(
        attn_p, wprojr_p, b_proj, out, MTOT, DD, DD);
}